// round 5
// baseline (speedup 1.0000x reference)
#include <cuda_runtime.h>
#include <cuda_fp16.h>
#include <cstddef>

#define GH 1024
#define GW 1024
#define GC 32
#define GHW (GH * GW)

// 64 MB transposed fp16 params: [HW, C]. Each grid cell's 32 channels are one
// contiguous 64B block; working set fits L2 during the gather.
__device__ __half g_params_h[(size_t)GHW * GC];

// ---------------------------------------------------------------------------
// Kernel 1: transpose + convert, no smem. One thread = one point.
// Warp reads 128B coalesced per channel (32 independent loads in flight per
// thread), converts to fp16, writes 64B contiguous per point (warp: 2KB).
// ---------------------------------------------------------------------------
__global__ void transpose_kernel(const float* __restrict__ in) {
    const int p = blockIdx.x * blockDim.x + threadIdx.x;  // point 0..GHW-1

    float v[32];
#pragma unroll
    for (int c = 0; c < 32; c++) {
        v[c] = __ldcs(in + (size_t)c * GHW + p);
    }

    uint4* __restrict__ outv = (uint4*)(g_params_h + (size_t)p * GC);
#pragma unroll
    for (int q = 0; q < 4; q++) {
        union { __half2 h2[4]; uint4 u; } pack;
#pragma unroll
        for (int j = 0; j < 4; j++) {
            pack.h2[j] = __floats2half2_rn(v[q * 8 + 2 * j], v[q * 8 + 2 * j + 1]);
        }
        outv[q] = pack.u;
    }
}

// ---------------------------------------------------------------------------
// Kernel 2: bilinear gather, 2 points per thread, 4 lanes per point.
// Each thread keeps 8 independent LDG.128 in flight (128B MLP/thread).
// ---------------------------------------------------------------------------
__global__ void __launch_bounds__(256)
gather_kernel(const float* __restrict__ coord,
              float* __restrict__ out,
              int n_points) {
    const int t   = blockIdx.x * blockDim.x + threadIdx.x;
    const int g   = t >> 2;          // pair-group index
    const int sub = t & 3;           // channel slice (8 channels)
    const int pA  = g * 2;
    const int pB  = pA + 1;
    if (pA >= n_points) return;

    // Coord pair: one float4 = {xA, yA, xB, yB}. (4 lanes broadcast-load.)
    const float4 cc = __ldg(((const float4*)coord) + g);

    // --- point A setup ---
    const float ixA = (cc.x + 1.0f) * 0.5f * (float)(GW - 1);
    const float iyA = (cc.y + 1.0f) * 0.5f * (float)(GH - 1);
    const float fxA = floorf(ixA), fyA = floorf(iyA);
    const float ax1 = ixA - fxA, ay1 = iyA - fyA;
    const float ax0 = 1.0f - ax1, ay0 = 1.0f - ay1;
    int Ax0 = (int)fxA; Ax0 = Ax0 < 0 ? 0 : (Ax0 > GW - 1 ? GW - 1 : Ax0);
    int Ay0 = (int)fyA; Ay0 = Ay0 < 0 ? 0 : (Ay0 > GH - 1 ? GH - 1 : Ay0);
    int Ax1 = Ax0 + 1;  Ax1 = Ax1 > GW - 1 ? GW - 1 : Ax1;
    int Ay1 = Ay0 + 1;  Ay1 = Ay1 > GH - 1 ? GH - 1 : Ay1;

    // --- point B setup ---
    const float ixB = (cc.z + 1.0f) * 0.5f * (float)(GW - 1);
    const float iyB = (cc.w + 1.0f) * 0.5f * (float)(GH - 1);
    const float fxB = floorf(ixB), fyB = floorf(iyB);
    const float bx1 = ixB - fxB, by1 = iyB - fyB;
    const float bx0 = 1.0f - bx1, by0 = 1.0f - by1;
    int Bx0 = (int)fxB; Bx0 = Bx0 < 0 ? 0 : (Bx0 > GW - 1 ? GW - 1 : Bx0);
    int By0 = (int)fyB; By0 = By0 < 0 ? 0 : (By0 > GH - 1 ? GH - 1 : By0);
    int Bx1 = Bx0 + 1;  Bx1 = Bx1 > GW - 1 ? GW - 1 : Bx1;
    int By1 = By0 + 1;  By1 = By1 > GH - 1 ? GH - 1 : By1;

    // Issue all 8 corner loads (independent, 16B each).
    const uint4* __restrict__ base = (const uint4*)g_params_h;
    const uint4 A_nw = __ldg(base + ((Ay0 << 10) + Ax0) * 4 + sub);
    const uint4 A_ne = __ldg(base + ((Ay0 << 10) + Ax1) * 4 + sub);
    const uint4 A_sw = __ldg(base + ((Ay1 << 10) + Ax0) * 4 + sub);
    const uint4 A_se = __ldg(base + ((Ay1 << 10) + Ax1) * 4 + sub);
    const uint4 B_nw = __ldg(base + ((By0 << 10) + Bx0) * 4 + sub);
    const uint4 B_ne = __ldg(base + ((By0 << 10) + Bx1) * 4 + sub);
    const uint4 B_sw = __ldg(base + ((By1 << 10) + Bx0) * 4 + sub);
    const uint4 B_se = __ldg(base + ((By1 << 10) + Bx1) * 4 + sub);

    const float wAnw = ax0 * ay0, wAne = ax1 * ay0, wAsw = ax0 * ay1, wAse = ax1 * ay1;
    const float wBnw = bx0 * by0, wBne = bx1 * by0, wBsw = bx0 * by1, wBse = bx1 * by1;

    float oA[8], oB[8];
#pragma unroll
    for (int h = 0; h < 4; h++) {
        {
            const float2 a = __half22float2(*(const __half2*)&(&A_nw.x)[h]);
            const float2 b = __half22float2(*(const __half2*)&(&A_ne.x)[h]);
            const float2 c = __half22float2(*(const __half2*)&(&A_sw.x)[h]);
            const float2 d = __half22float2(*(const __half2*)&(&A_se.x)[h]);
            oA[2 * h + 0] = a.x * wAnw + b.x * wAne + c.x * wAsw + d.x * wAse;
            oA[2 * h + 1] = a.y * wAnw + b.y * wAne + c.y * wAsw + d.y * wAse;
        }
        {
            const float2 a = __half22float2(*(const __half2*)&(&B_nw.x)[h]);
            const float2 b = __half22float2(*(const __half2*)&(&B_ne.x)[h]);
            const float2 c = __half22float2(*(const __half2*)&(&B_sw.x)[h]);
            const float2 d = __half22float2(*(const __half2*)&(&B_se.x)[h]);
            oB[2 * h + 0] = a.x * wBnw + b.x * wBne + c.x * wBsw + d.x * wBse;
            oB[2 * h + 1] = a.y * wBnw + b.y * wBne + c.y * wBsw + d.y * wBse;
        }
    }

    // Streaming stores: warp covers 16 consecutive points -> 2KB contiguous.
    float4* __restrict__ ovA = ((float4*)out) + (size_t)pA * 8 + 2 * sub;
    __stcs(ovA + 0, make_float4(oA[0], oA[1], oA[2], oA[3]));
    __stcs(ovA + 1, make_float4(oA[4], oA[5], oA[6], oA[7]));
    if (pB < n_points) {
        float4* __restrict__ ovB = ((float4*)out) + (size_t)pB * 8 + 2 * sub;
        __stcs(ovB + 0, make_float4(oB[0], oB[1], oB[2], oB[3]));
        __stcs(ovB + 1, make_float4(oB[4], oB[5], oB[6], oB[7]));
    }
}

extern "C" void kernel_launch(void* const* d_in, const int* in_sizes, int n_in,
                              void* d_out, int out_size) {
    const float* coord;
    const float* params;
    int coord_elems;
    if (in_sizes[0] < in_sizes[1]) {
        coord = (const float*)d_in[0];
        params = (const float*)d_in[1];
        coord_elems = in_sizes[0];
    } else {
        coord = (const float*)d_in[1];
        params = (const float*)d_in[0];
        coord_elems = in_sizes[1];
    }
    const int n_points = coord_elems / 2;

    transpose_kernel<<<GHW / 256, 256>>>(params);

    const int n_pairs = (n_points + 1) / 2;
    const int total_threads = n_pairs * 4;
    const int block = 256;
    const int grid = (total_threads + block - 1) / block;
    gather_kernel<<<grid, block>>>(coord, (float*)d_out, n_points);
}

// round 6
// speedup vs baseline: 1.0262x; 1.0262x over previous
#include <cuda_runtime.h>
#include <cuda_fp16.h>
#include <cstddef>

#define GH 1024
#define GW 1024
#define GC 32
#define GHW (GH * GW)

// 64 MB transposed fp16 params: [HW, C]. Each grid cell's 32 channels are one
// contiguous 64B block; working set fits L2 during the gather.
__device__ __half g_params_h[(size_t)GHW * GC];

// ---------------------------------------------------------------------------
// Kernel 1: transpose + convert, no smem. One thread = one point.
// ---------------------------------------------------------------------------
__global__ void transpose_kernel(const float* __restrict__ in) {
    const int p = blockIdx.x * blockDim.x + threadIdx.x;

    float v[32];
#pragma unroll
    for (int c = 0; c < 32; c++) {
        v[c] = __ldcs(in + (size_t)c * GHW + p);
    }

    uint4* __restrict__ outv = (uint4*)(g_params_h + (size_t)p * GC);
#pragma unroll
    for (int q = 0; q < 4; q++) {
        union { __half2 h2[4]; uint4 u; } pack;
#pragma unroll
        for (int j = 0; j < 4; j++) {
            pack.h2[j] = __floats2half2_rn(v[q * 8 + 2 * j], v[q * 8 + 2 * j + 1]);
        }
        outv[q] = pack.u;
    }
}

// L2-only 16B load (skip L1: ~0% hit rate on 64MB random working set).
__device__ __forceinline__ uint4 ldcg16(const uint4* p) {
    uint4 r;
    asm volatile("ld.global.cg.v4.u32 {%0,%1,%2,%3}, [%4];"
                 : "=r"(r.x), "=r"(r.y), "=r"(r.z), "=r"(r.w) : "l"(p));
    return r;
}

// ---------------------------------------------------------------------------
// Kernel 2: bilinear gather, 2 points per thread, 4 lanes per point.
// __launch_bounds__(256, 4): 64-reg budget so all 8 corner loads stay in
// flight simultaneously (128B MLP per thread).
// ---------------------------------------------------------------------------
__global__ void __launch_bounds__(256, 4)
gather_kernel(const float* __restrict__ coord,
              float* __restrict__ out,
              int n_points) {
    const int t   = blockIdx.x * blockDim.x + threadIdx.x;
    const int g   = t >> 2;          // pair-group index
    const int sub = t & 3;           // channel slice (8 channels)
    const int pA  = g * 2;
    const int pB  = pA + 1;
    if (pA >= n_points) return;

    const float4 cc = __ldg(((const float4*)coord) + g);  // {xA,yA,xB,yB}

    // --- point A ---
    const float ixA = (cc.x + 1.0f) * 0.5f * (float)(GW - 1);
    const float iyA = (cc.y + 1.0f) * 0.5f * (float)(GH - 1);
    const float fxA = floorf(ixA), fyA = floorf(iyA);
    const float ax1 = ixA - fxA, ay1 = iyA - fyA;
    const float ax0 = 1.0f - ax1, ay0 = 1.0f - ay1;
    int Ax0 = (int)fxA; Ax0 = Ax0 < 0 ? 0 : (Ax0 > GW - 1 ? GW - 1 : Ax0);
    int Ay0 = (int)fyA; Ay0 = Ay0 < 0 ? 0 : (Ay0 > GH - 1 ? GH - 1 : Ay0);
    int Ax1 = Ax0 + 1;  Ax1 = Ax1 > GW - 1 ? GW - 1 : Ax1;
    int Ay1 = Ay0 + 1;  Ay1 = Ay1 > GH - 1 ? GH - 1 : Ay1;

    // --- point B ---
    const float ixB = (cc.z + 1.0f) * 0.5f * (float)(GW - 1);
    const float iyB = (cc.w + 1.0f) * 0.5f * (float)(GH - 1);
    const float fxB = floorf(ixB), fyB = floorf(iyB);
    const float bx1 = ixB - fxB, by1 = iyB - fyB;
    const float bx0 = 1.0f - bx1, by0 = 1.0f - by1;
    int Bx0 = (int)fxB; Bx0 = Bx0 < 0 ? 0 : (Bx0 > GW - 1 ? GW - 1 : Bx0);
    int By0 = (int)fyB; By0 = By0 < 0 ? 0 : (By0 > GH - 1 ? GH - 1 : By0);
    int Bx1 = Bx0 + 1;  Bx1 = Bx1 > GW - 1 ? GW - 1 : Bx1;
    int By1 = By0 + 1;  By1 = By1 > GH - 1 ? GH - 1 : By1;

    // Issue all 8 independent 16B corner loads before consuming any.
    const uint4* __restrict__ base = (const uint4*)g_params_h;
    const uint4 A_nw = ldcg16(base + ((Ay0 << 10) + Ax0) * 4 + sub);
    const uint4 A_ne = ldcg16(base + ((Ay0 << 10) + Ax1) * 4 + sub);
    const uint4 A_sw = ldcg16(base + ((Ay1 << 10) + Ax0) * 4 + sub);
    const uint4 A_se = ldcg16(base + ((Ay1 << 10) + Ax1) * 4 + sub);
    const uint4 B_nw = ldcg16(base + ((By0 << 10) + Bx0) * 4 + sub);
    const uint4 B_ne = ldcg16(base + ((By0 << 10) + Bx1) * 4 + sub);
    const uint4 B_sw = ldcg16(base + ((By1 << 10) + Bx0) * 4 + sub);
    const uint4 B_se = ldcg16(base + ((By1 << 10) + Bx1) * 4 + sub);

    const float wAnw = ax0 * ay0, wAne = ax1 * ay0, wAsw = ax0 * ay1, wAse = ax1 * ay1;
    const float wBnw = bx0 * by0, wBne = bx1 * by0, wBsw = bx0 * by1, wBse = bx1 * by1;

    float oA[8], oB[8];
#pragma unroll
    for (int h = 0; h < 4; h++) {
        {
            const float2 a = __half22float2(*(const __half2*)&(&A_nw.x)[h]);
            const float2 b = __half22float2(*(const __half2*)&(&A_ne.x)[h]);
            const float2 c = __half22float2(*(const __half2*)&(&A_sw.x)[h]);
            const float2 d = __half22float2(*(const __half2*)&(&A_se.x)[h]);
            oA[2 * h + 0] = a.x * wAnw + b.x * wAne + c.x * wAsw + d.x * wAse;
            oA[2 * h + 1] = a.y * wAnw + b.y * wAne + c.y * wAsw + d.y * wAse;
        }
        {
            const float2 a = __half22float2(*(const __half2*)&(&B_nw.x)[h]);
            const float2 b = __half22float2(*(const __half2*)&(&B_ne.x)[h]);
            const float2 c = __half22float2(*(const __half2*)&(&B_sw.x)[h]);
            const float2 d = __half22float2(*(const __half2*)&(&B_se.x)[h]);
            oB[2 * h + 0] = a.x * wBnw + b.x * wBne + c.x * wBsw + d.x * wBse;
            oB[2 * h + 1] = a.y * wBnw + b.y * wBne + c.y * wBsw + d.y * wBse;
        }
    }

    float4* __restrict__ ovA = ((float4*)out) + (size_t)pA * 8 + 2 * sub;
    __stcs(ovA + 0, make_float4(oA[0], oA[1], oA[2], oA[3]));
    __stcs(ovA + 1, make_float4(oA[4], oA[5], oA[6], oA[7]));
    if (pB < n_points) {
        float4* __restrict__ ovB = ((float4*)out) + (size_t)pB * 8 + 2 * sub;
        __stcs(ovB + 0, make_float4(oB[0], oB[1], oB[2], oB[3]));
        __stcs(ovB + 1, make_float4(oB[4], oB[5], oB[6], oB[7]));
    }
}

extern "C" void kernel_launch(void* const* d_in, const int* in_sizes, int n_in,
                              void* d_out, int out_size) {
    const float* coord;
    const float* params;
    int coord_elems;
    if (in_sizes[0] < in_sizes[1]) {
        coord = (const float*)d_in[0];
        params = (const float*)d_in[1];
        coord_elems = in_sizes[0];
    } else {
        coord = (const float*)d_in[1];
        params = (const float*)d_in[0];
        coord_elems = in_sizes[1];
    }
    const int n_points = coord_elems / 2;

    transpose_kernel<<<GHW / 256, 256>>>(params);

    const int n_pairs = (n_points + 1) / 2;
    const int total_threads = n_pairs * 4;
    const int block = 256;
    const int grid = (total_threads + block - 1) / block;
    gather_kernel<<<grid, block>>>(coord, (float*)d_out, n_points);
}

// round 7
// speedup vs baseline: 1.0353x; 1.0089x over previous
#include <cuda_runtime.h>
#include <cuda_fp16.h>
#include <cstddef>

#define GH 1024
#define GW 1024
#define GC 32
#define GHW (GH * GW)

// 64 MB transposed fp16 params: [HW, C]. Each grid cell's 32 channels are one
// contiguous 64B block; working set fits L2 during the gather.
__device__ __half g_params_h[(size_t)GHW * GC];

// ---------------------------------------------------------------------------
// Kernel 1: transpose + convert, no smem. One thread = one point.
// ---------------------------------------------------------------------------
__global__ void transpose_kernel(const float* __restrict__ in) {
    const int p = blockIdx.x * blockDim.x + threadIdx.x;

    float v[32];
#pragma unroll
    for (int c = 0; c < 32; c++) {
        v[c] = __ldcs(in + (size_t)c * GHW + p);
    }

    uint4* __restrict__ outv = (uint4*)(g_params_h + (size_t)p * GC);
#pragma unroll
    for (int q = 0; q < 4; q++) {
        union { __half2 h2[4]; uint4 u; } pack;
#pragma unroll
        for (int j = 0; j < 4; j++) {
            pack.h2[j] = __floats2half2_rn(v[q * 8 + 2 * j], v[q * 8 + 2 * j + 1]);
        }
        outv[q] = pack.u;
    }
}

// L2-only 16B load (skip L1: ~0% hit rate on 64MB random working set).
__device__ __forceinline__ uint4 ldcg16(const uint4* p) {
    uint4 r;
    asm volatile("ld.global.cg.v4.u32 {%0,%1,%2,%3}, [%4];"
                 : "=r"(r.x), "=r"(r.y), "=r"(r.z), "=r"(r.w) : "l"(p));
    return r;
}

// ---------------------------------------------------------------------------
// Kernel 2: bilinear gather (R4 structure: 4 lanes per point, 4x LDG.128,
// 32 regs, high occupancy). Output via write-through stores so the 256MB
// output stream does not allocate L2 lines and evict the 64MB param set.
// ---------------------------------------------------------------------------
__global__ void __launch_bounds__(256)
gather_kernel(const float* __restrict__ coord,
              float* __restrict__ out,
              int n_points) {
    const int t   = blockIdx.x * blockDim.x + threadIdx.x;
    const int p   = t >> 2;
    const int sub = t & 3;          // 8 channels per lane
    if (p >= n_points) return;

    const float2 xy = __ldcs(((const float2*)coord) + p);

    const float ix = (xy.x + 1.0f) * 0.5f * (float)(GW - 1);
    const float iy = (xy.y + 1.0f) * 0.5f * (float)(GH - 1);

    const float fx0 = floorf(ix);
    const float fy0 = floorf(iy);
    const float wx1 = ix - fx0;
    const float wy1 = iy - fy0;
    const float wx0 = 1.0f - wx1;
    const float wy0 = 1.0f - wy1;

    int x0 = (int)fx0; x0 = x0 < 0 ? 0 : (x0 > GW - 1 ? GW - 1 : x0);
    int y0 = (int)fy0; y0 = y0 < 0 ? 0 : (y0 > GH - 1 ? GH - 1 : y0);
    int x1 = x0 + 1;   x1 = x1 > GW - 1 ? GW - 1 : x1;
    int y1 = y0 + 1;   y1 = y1 > GH - 1 ? GH - 1 : y1;

    const float w_nw = wx0 * wy0;
    const float w_ne = wx1 * wy0;
    const float w_sw = wx0 * wy1;
    const float w_se = wx1 * wy1;

    const uint4* __restrict__ base = (const uint4*)g_params_h;
    const uint4 r_nw = ldcg16(base + (((size_t)y0 << 10) + x0) * 4 + sub);
    const uint4 r_ne = ldcg16(base + (((size_t)y0 << 10) + x1) * 4 + sub);
    const uint4 r_sw = ldcg16(base + (((size_t)y1 << 10) + x0) * 4 + sub);
    const uint4 r_se = ldcg16(base + (((size_t)y1 << 10) + x1) * 4 + sub);

    float o[8];
#pragma unroll
    for (int h = 0; h < 4; h++) {
        const unsigned ua = (&r_nw.x)[h];
        const unsigned ub = (&r_ne.x)[h];
        const unsigned uc = (&r_sw.x)[h];
        const unsigned ud = (&r_se.x)[h];
        const float2 a = __half22float2(*(const __half2*)&ua);
        const float2 b = __half22float2(*(const __half2*)&ub);
        const float2 c = __half22float2(*(const __half2*)&uc);
        const float2 d = __half22float2(*(const __half2*)&ud);
        o[2 * h + 0] = a.x * w_nw + b.x * w_ne + c.x * w_sw + d.x * w_se;
        o[2 * h + 1] = a.y * w_nw + b.y * w_ne + c.y * w_sw + d.y * w_se;
    }

    // Write-through stores: don't establish output lines in L2, so the 64MB
    // param set stays resident. Each thread writes 32B contiguous.
    float4* __restrict__ ov = ((float4*)out) + (size_t)p * 8 + 2 * sub;
    __stwt(ov + 0, make_float4(o[0], o[1], o[2], o[3]));
    __stwt(ov + 1, make_float4(o[4], o[5], o[6], o[7]));
}

extern "C" void kernel_launch(void* const* d_in, const int* in_sizes, int n_in,
                              void* d_out, int out_size) {
    const float* coord;
    const float* params;
    int coord_elems;
    if (in_sizes[0] < in_sizes[1]) {
        coord = (const float*)d_in[0];
        params = (const float*)d_in[1];
        coord_elems = in_sizes[0];
    } else {
        coord = (const float*)d_in[1];
        params = (const float*)d_in[0];
        coord_elems = in_sizes[1];
    }
    const int n_points = coord_elems / 2;

    transpose_kernel<<<GHW / 256, 256>>>(params);

    const int total_threads = n_points * 4;
    const int block = 256;
    const int grid = (total_threads + block - 1) / block;
    gather_kernel<<<grid, block>>>(coord, (float*)d_out, n_points);
}